// round 11
// baseline (speedup 1.0000x reference)
#include <cuda_runtime.h>
#include <math.h>

// x (2,16,256,256) f32, conv_w (32,16,4,4), conv_b (32) -> out (2,32,256,256) f32.
// Ring of 40 offsets (radius 5), stable-select 16 smallest sigmoid-sims,
// rank-indexed 32x(16*16) mat-vec per pixel.
// TWO kernels so each phase gets its own register budget:
//   K1 (sel_kernel):  sims + streaming stable rank -> g_sel (u16 per rank)
//   K2 (conv_kernel): R6-proven pixel-pair/half-OUTC mat-vec
// Phase-1 arithmetic bit-exact vs proven baseline (rel_err 6.692e-4).

#define B_      2
#define CCH     16
#define NC2     (CCH/2)        // 8 float2 channel-pairs
#define HH      256
#define WWIDTH  256
#define HW      (HH*WWIDTH)
#define OUTC    32
#define NOFF    40
#define NSEL    16

#define TW 32
#define TH 8
#define NTHR (TW*TH)           // 256
#define GRIDX (WWIDTH/TW)      // 8
#define GRIDY (HH/TH)          // 32
#define NBLK  (GRIDX*GRIDY*B_) // 512
#define SW 42
#define SH 18
#define CPLANE (SW*SH)         // 756
#define XS_FLOATS (CPLANE*CCH)        // 12096
#define WS_FLOATS (NSEL*CCH*OUTC)     // 8192
#define CB_FLOATS 32
#define SEL_U32_PER_BLK (NTHR*NSEL/2) // 2048

#define SMEM1 (XS_FLOATS*4 + NTHR*NSEL*2)                      // 56576
#define SMEM2 ((XS_FLOATS + WS_FLOATS + CB_FLOATS)*4 + NTHR*NSEL*2) // 89472

// Ring offsets, order matching _prf_offsets:
//  j 0..10 : dx=-5,   dy=j-5
//  j 11..19: dx=j-15, dy=+5
//  j 20..30: dx=+5,   dy=j-25
//  j 31..39: dx=j-35, dy=-5
__host__ __device__ constexpr int dxOf(int j){ return j<11 ? -5 : (j<20 ? j-15 : (j<31 ? 5 : j-35)); }
__host__ __device__ constexpr int dyOf(int j){ return j<11 ? j-5 : (j<20 ? 5 : (j<31 ? j-25 : -5)); }
__host__ __device__ constexpr int offOf(int j){ return dxOf(j)*SW + dyOf(j); }

typedef unsigned long long u64;

// selection scratch: [block][rank][tid] u16 (offset+512)
__device__ __align__(16) unsigned short g_sel[NBLK * NTHR * NSEL];

__device__ __forceinline__ u64 pack2(float a, float b){
    u64 r;
    asm("mov.b64 %0, {%1,%2};" : "=l"(r) : "f"(a), "f"(b));
    return r;
}
__device__ __forceinline__ void fma2(u64 &acc, u64 a, u64 b){
    asm("fma.rn.f32x2 %0, %1, %2, %0;" : "+l"(acc) : "l"(a), "l"(b));
}
__device__ __forceinline__ float2 unpack2(u64 v){
    float2 f;
    asm("mov.b64 {%0,%1}, %2;" : "=f"(f.x), "=f"(f.y) : "l"(v));
    return f;
}

__device__ __forceinline__ void load_halo(float2* xs2, const float* xb,
                                          int tid, int gx0, int gy0)
{
    for (int i = tid; i < CPLANE*NC2; i += NTHR) {
        int c2  = i / CPLANE;
        int rem = i - c2*CPLANE;
        int sy  = rem / SW;
        int sx  = rem - sy*SW;
        int gy  = gy0 + sy - 5;
        int gxp = gx0 + sx - 5;
        float2 v = make_float2(0.f, 0.f);
        if ((unsigned)gy < (unsigned)HH && (unsigned)gxp < (unsigned)WWIDTH) {
            const float* p = xb + (2*c2)*HW + gy*WWIDTH + gxp;
            v.x = p[0];
            v.y = p[HW];
        }
        xs2[i] = v;
    }
}

// ================= K1: selection =================
__global__ __launch_bounds__(NTHR, 3)
void sel_kernel(const float* __restrict__ x)
{
    extern __shared__ float sm[];
    float2*         xs2  = reinterpret_cast<float2*>(sm);
    unsigned short* sels = (unsigned short*)(sm + XS_FLOATS); // [rank][tid]

    const int tx = threadIdx.x, ty = threadIdx.y;
    const int tid = ty*TW + tx;
    const int gx0 = blockIdx.x*TW, gy0 = blockIdx.y*TH;
    const int bz  = blockIdx.z;

    load_halo(xs2, x + (size_t)bz * CCH * HW, tid, gx0, gy0);
    __syncthreads();

    const int base = (ty+5)*SW + (tx+5);

    float2 xc[NC2];
    #pragma unroll
    for (int c2 = 0; c2 < NC2; ++c2) xc[c2] = xs2[c2*CPLANE + base];

    // sims: sequential channel-order mul+add (matches reference reduction),
    // then sigmoid — REQUIRED: its fp32 rounding creates index-broken ties
    // (verified R5). __frcp_rn bit-identical to 1.0f/x (verified R9).
    float sims[NOFF];
    #pragma unroll
    for (int j = 0; j < NOFF; ++j) {
        const int off = offOf(j);
        float s = 0.f;
        #pragma unroll
        for (int c2 = 0; c2 < NC2; ++c2) {
            const float2 v = xs2[c2*CPLANE + base + off];
            s = __fadd_rn(s, __fmul_rn(v.x, xc[c2].x));
            s = __fadd_rn(s, __fmul_rn(v.y, xc[c2].y));
        }
        s *= 0.0625f;
        sims[j] = __frcp_rn(1.0f + expf(-s));
    }

    // Streaming stable-argsort rank (no rk[] array -> low reg pressure):
    // rank_j = #{i<j: s_i<=s_j} + #{i>j: s_i<s_j}   (verified R8: identical)
    #pragma unroll
    for (int j = 0; j < NOFF; ++j) {
        int rk = 0;
        #pragma unroll
        for (int i = 0; i < NOFF; ++i) {
            if (i < j)       rk += (sims[i] <= sims[j]) ? 1 : 0;
            else if (i > j)  rk += (sims[i] <  sims[j]) ? 1 : 0;
        }
        if (rk < NSEL)
            sels[rk*NTHR + tid] = (unsigned short)(offOf(j) + 512);
    }
    __syncthreads();

    // coalesced copy to global
    const int blkid = (bz*GRIDY + blockIdx.y)*GRIDX + blockIdx.x;
    unsigned* dst = reinterpret_cast<unsigned*>(g_sel) + blkid*SEL_U32_PER_BLK;
    const unsigned* src = reinterpret_cast<const unsigned*>(sels);
    for (int i = tid; i < SEL_U32_PER_BLK; i += NTHR) dst[i] = src[i];
}

// ================= K2: rank-indexed mat-vec (R6-proven body) =================
__global__ __launch_bounds__(NTHR, 2)
void conv_kernel(const float* __restrict__ x,
                 const float* __restrict__ cw,
                 const float* __restrict__ cb,
                 float* __restrict__ out)
{
    extern __shared__ float sm[];
    float2*         xs2  = reinterpret_cast<float2*>(sm);
    float*          ws   = sm + XS_FLOATS;                     // [r][c][o]
    float*          cbs  = ws + WS_FLOATS;                     // [32]
    unsigned short* selp = (unsigned short*)(cbs + CB_FLOATS); // [rank][tid]

    const int tx = threadIdx.x, ty = threadIdx.y;
    const int tid = ty*TW + tx;
    const int gx0 = blockIdx.x*TW, gy0 = blockIdx.y*TH;
    const int bz  = blockIdx.z;

    load_halo(xs2, x + (size_t)bz * CCH * HW, tid, gx0, gy0);
    // ws[((r*16)+c)*32 + o] = cw[o*256 + c*16 + r]
    for (int i = tid; i < WS_FLOATS; i += NTHR) {
        int o  = i & 31;
        int rc = i >> 5;
        int r  = rc >> 4;
        int c  = rc & 15;
        ws[i] = cw[o*256 + c*16 + r];
    }
    if (tid < 32) cbs[tid] = cb[tid];
    // stage selections (coalesced)
    {
        const int blkid = (bz*GRIDY + blockIdx.y)*GRIDX + blockIdx.x;
        const unsigned* src = reinterpret_cast<const unsigned*>(g_sel)
                            + blkid*SEL_U32_PER_BLK;
        unsigned* dst = reinterpret_cast<unsigned*>(selp);
        for (int i = tid; i < SEL_U32_PER_BLK; i += NTHR) dst[i] = src[i];
    }
    __syncthreads();

    // pixel-pair / half-OUTC split (crossbar-optimal, proven R6)
    const int pp = tid & 127;
    const int ph = tid >> 7;
    const int px = pp & 31;
    const int py = pp >> 5;

    const int b0 = (py+5)*SW + (px+5);
    const int b1 = b0 + 4*SW;

    float2 xc0[NC2], xc1[NC2];
    #pragma unroll
    for (int c2 = 0; c2 < NC2; ++c2) {
        xc0[c2] = xs2[c2*CPLANE + b0];
        xc1[c2] = xs2[c2*CPLANE + b1];
    }

    u64 accA[8], accB[8];
    #pragma unroll
    for (int q = 0; q < 8; ++q) {
        u64 seed = pack2(cbs[ph*16 + 2*q], cbs[ph*16 + 2*q + 1]);
        accA[q] = seed;
        accB[q] = seed;
    }

    #pragma unroll 1
    for (int r = 0; r < NSEL; ++r) {
        const int a0 = b0 + (int)selp[r*NTHR + pp]       - 512;
        const int a1 = b1 + (int)selp[r*NTHR + pp + 128] - 512;
        const ulonglong2* wp =
            reinterpret_cast<const ulonglong2*>(ws + (r << 9) + (ph << 4));
        #pragma unroll
        for (int c2 = 0; c2 < NC2; ++c2) {
            const float2 v0 = xs2[c2*CPLANE + a0];
            const float2 v1 = xs2[c2*CPLANE + a1];
            const u64 dx0 = pack2(xc0[c2].x - v0.x, xc0[c2].x - v0.x);
            const u64 dy0 = pack2(xc0[c2].y - v0.y, xc0[c2].y - v0.y);
            const u64 dx1 = pack2(xc1[c2].x - v1.x, xc1[c2].x - v1.x);
            const u64 dy1 = pack2(xc1[c2].y - v1.y, xc1[c2].y - v1.y);
            const ulonglong2* cA = wp + (2*c2  )*8;
            const ulonglong2* cB = wp + (2*c2+1)*8;
            ulonglong2 wa = cA[0], wb = cA[1], wc = cA[2], wd = cA[3];
            fma2(accA[0], wa.x, dx0); fma2(accB[0], wa.x, dx1);
            fma2(accA[1], wa.y, dx0); fma2(accB[1], wa.y, dx1);
            fma2(accA[2], wb.x, dx0); fma2(accB[2], wb.x, dx1);
            fma2(accA[3], wb.y, dx0); fma2(accB[3], wb.y, dx1);
            fma2(accA[4], wc.x, dx0); fma2(accB[4], wc.x, dx1);
            fma2(accA[5], wc.y, dx0); fma2(accB[5], wc.y, dx1);
            fma2(accA[6], wd.x, dx0); fma2(accB[6], wd.x, dx1);
            fma2(accA[7], wd.y, dx0); fma2(accB[7], wd.y, dx1);
            wa = cB[0]; wb = cB[1]; wc = cB[2]; wd = cB[3];
            fma2(accA[0], wa.x, dy0); fma2(accB[0], wa.x, dy1);
            fma2(accA[1], wa.y, dy0); fma2(accB[1], wa.y, dy1);
            fma2(accA[2], wb.x, dy0); fma2(accB[2], wb.x, dy1);
            fma2(accA[3], wb.y, dy0); fma2(accB[3], wb.y, dy1);
            fma2(accA[4], wc.x, dy0); fma2(accB[4], wc.x, dy1);
            fma2(accA[5], wc.y, dy0); fma2(accB[5], wc.y, dy1);
            fma2(accA[6], wd.x, dy0); fma2(accB[6], wd.x, dy1);
            fma2(accA[7], wd.y, dy0); fma2(accB[7], wd.y, dy1);
        }
    }

    // ---- store: 16 o-channels x 2 pixels ----
    const int gx = gx0 + px;
    const int gy_a = gy0 + py;
    const int gy_b = gy_a + 4;
    float* ob = out + (size_t)bz*OUTC*HW + (size_t)(ph*16)*HW + gx;
    #pragma unroll
    for (int q = 0; q < 8; ++q) {
        float2 va = unpack2(accA[q]);
        float2 vb = unpack2(accB[q]);
        ob[(2*q  )*HW + gy_a*WWIDTH] = va.x;
        ob[(2*q+1)*HW + gy_a*WWIDTH] = va.y;
        ob[(2*q  )*HW + gy_b*WWIDTH] = vb.x;
        ob[(2*q+1)*HW + gy_b*WWIDTH] = vb.y;
    }
}

extern "C" void kernel_launch(void* const* d_in, const int* in_sizes, int n_in,
                              void* d_out, int out_size)
{
    const float* x  = (const float*)d_in[0];
    const float* cw = (const float*)d_in[1];
    const float* cb = (const float*)d_in[2];
    float* out = (float*)d_out;

    cudaFuncSetAttribute(sel_kernel,
                         cudaFuncAttributeMaxDynamicSharedMemorySize, SMEM1);
    cudaFuncSetAttribute(conv_kernel,
                         cudaFuncAttributeMaxDynamicSharedMemorySize, SMEM2);

    dim3 block(TW, TH, 1);
    dim3 grid(GRIDX, GRIDY, B_);
    sel_kernel<<<grid, block, SMEM1>>>(x);
    conv_kernel<<<grid, block, SMEM2>>>(x, cw, cb, out);
}

// round 12
// speedup vs baseline: 1.1394x; 1.1394x over previous
#include <cuda_runtime.h>
#include <math.h>

// x (2,16,256,256) f32, conv_w (32,16,4,4), conv_b (32) -> out (2,32,256,256) f32.
// Ring of 40 offsets (radius 5), stable-select 16 smallest sigmoid-sims,
// rank-indexed 32x(16*16) mat-vec per pixel.
// Fused kernel (R6 structure) with float4 channel-grouped halo:
// xs4[c4][plane] holds channels 4c4..4c4+3 per 16B -> LDS.128 gathers.
// Phase-1 arithmetic bit-exact vs proven baseline (rel_err 6.692e-4).

#define B_      2
#define CCH     16
#define NC4     (CCH/4)        // 4 float4 channel-groups
#define HH      256
#define WWIDTH  256
#define HW      (HH*WWIDTH)
#define OUTC    32
#define NOFF    40
#define NSEL    16

#define TW 32
#define TH 8
#define NTHR (TW*TH)           // 256
#define SW 42                  // TW + 2*5
#define SH 18                  // TH + 2*5
#define CPLANE (SW*SH)         // 756
#define XS_FLOATS (CPLANE*CCH)        // 12096
#define WS_FLOATS (NSEL*CCH*OUTC)     // 8192
#define CB_FLOATS 32
// smem: xs + ws + cbs + selp(u16 [rank][tid] = 8192B)
#define SMEM_BYTES ((XS_FLOATS + WS_FLOATS + CB_FLOATS)*4 + NSEL*NTHR*2)

// Ring offsets, order matching _prf_offsets:
//  j 0..10 : dx=-5,   dy=j-5
//  j 11..19: dx=j-15, dy=+5
//  j 20..30: dx=+5,   dy=j-25
//  j 31..39: dx=j-35, dy=-5
__host__ __device__ constexpr int dxOf(int j){ return j<11 ? -5 : (j<20 ? j-15 : (j<31 ? 5 : j-35)); }
__host__ __device__ constexpr int dyOf(int j){ return j<11 ? j-5 : (j<20 ? 5 : (j<31 ? j-25 : -5)); }
__host__ __device__ constexpr int offOf(int j){ return dxOf(j)*SW + dyOf(j); }

typedef unsigned long long u64;

__device__ __forceinline__ u64 pack2(float a, float b){
    u64 r;
    asm("mov.b64 %0, {%1,%2};" : "=l"(r) : "f"(a), "f"(b));
    return r;
}
__device__ __forceinline__ void fma2(u64 &acc, u64 a, u64 b){
    asm("fma.rn.f32x2 %0, %1, %2, %0;" : "+l"(acc) : "l"(a), "l"(b));
}
__device__ __forceinline__ float2 unpack2(u64 v){
    float2 f;
    asm("mov.b64 {%0,%1}, %2;" : "=f"(f.x), "=f"(f.y) : "l"(v));
    return f;
}

__global__ __launch_bounds__(NTHR, 2)
void pkc2d_kernel(const float* __restrict__ x,
                  const float* __restrict__ cw,
                  const float* __restrict__ cb,
                  float* __restrict__ out)
{
    extern __shared__ float sm[];
    float4*         xs4  = reinterpret_cast<float4*>(sm);       // [c4][plane]
    float*          ws   = sm + XS_FLOATS;                      // [r][c][o]
    float*          cbs  = ws + WS_FLOATS;                      // [32]
    unsigned short* selp = (unsigned short*)(cbs + CB_FLOATS);  // [rank][tid]

    const int tx = threadIdx.x, ty = threadIdx.y;
    const int tid = ty*TW + tx;
    const int gx0 = blockIdx.x*TW, gy0 = blockIdx.y*TH;
    const int bz  = blockIdx.z;

    const float* xb = x + (size_t)bz * CCH * HW;

    // ---- cooperative halo load: 4-channel float4 groups ----
    for (int i = tid; i < CPLANE*NC4; i += NTHR) {
        int c4   = i / CPLANE;
        int cell = i - c4*CPLANE;
        int sy   = cell / SW;
        int sx   = cell - sy*SW;
        int gy   = gy0 + sy - 5;
        int gxp  = gx0 + sx - 5;
        float4 v = make_float4(0.f, 0.f, 0.f, 0.f);
        if ((unsigned)gy < (unsigned)HH && (unsigned)gxp < (unsigned)WWIDTH) {
            const float* p = xb + (4*c4)*HW + gy*WWIDTH + gxp;
            v.x = p[0];
            v.y = p[HW];
            v.z = p[2*HW];
            v.w = p[3*HW];
        }
        xs4[i] = v;
    }
    // ws[((r*16)+c)*32 + o] = cw[o*256 + c*16 + r]
    for (int i = tid; i < WS_FLOATS; i += NTHR) {
        int o  = i & 31;
        int rc = i >> 5;
        int r  = rc >> 4;
        int c  = rc & 15;
        ws[i] = cw[o*256 + c*16 + r];
    }
    if (tid < 32) cbs[tid] = cb[tid];
    __syncthreads();

    // ================= Phase 1: selection (bit-exact, proven) =================
    {
        const int base = (ty+5)*SW + (tx+5);

        float4 xc[NC4];
        #pragma unroll
        for (int c4 = 0; c4 < NC4; ++c4) xc[c4] = xs4[c4*CPLANE + base];

        // sims: sequential channel-order mul+add (matches reference reduction),
        // then sigmoid — REQUIRED: its fp32 rounding creates index-broken ties
        // (verified R5). __frcp_rn bit-identical to 1.0f/x (verified R9).
        float sims[NOFF];
        #pragma unroll
        for (int j = 0; j < NOFF; ++j) {
            const int off = offOf(j);
            float s = 0.f;
            #pragma unroll
            for (int c4 = 0; c4 < NC4; ++c4) {
                const float4 v = xs4[c4*CPLANE + base + off];
                s = __fadd_rn(s, __fmul_rn(v.x, xc[c4].x));
                s = __fadd_rn(s, __fmul_rn(v.y, xc[c4].y));
                s = __fadd_rn(s, __fmul_rn(v.z, xc[c4].z));
                s = __fadd_rn(s, __fmul_rn(v.w, xc[c4].w));
            }
            s *= 0.0625f;
            sims[j] = __frcp_rn(1.0f + expf(-s));
        }

        // Stable argsort rank, one compare per unordered pair (proven R4/R6).
        int rk[NOFF];
        #pragma unroll
        for (int i = 0; i < NOFF; ++i) rk[i] = NOFF - 1 - i;
        #pragma unroll
        for (int i = 0; i < NOFF; ++i) {
            #pragma unroll
            for (int j = i+1; j < NOFF; ++j) {
                if (sims[i] <= sims[j]) { rk[j] += 1; rk[i] -= 1; }
            }
        }
        #pragma unroll
        for (int j = 0; j < NOFF; ++j) {
            if (rk[j] < NSEL)
                selp[rk[j]*NTHR + tid] = (unsigned short)(offOf(j) + 512);
        }
    }
    __syncthreads();

    // ================= Phase 2: pixel-pair / half-OUTC mat-vec =================
    // thread t: ph = t>>7 -> o in [16*ph, 16*ph+16); pixels p0 = t&127 (rows 0..3)
    // and p1 = p0+128 (rows 4..7) of the 32x8 tile.
    const int pp = tid & 127;
    const int ph = tid >> 7;
    const int px = pp & 31;
    const int py = pp >> 5;

    const int b0 = (py+5)*SW + (px+5);
    const int b1 = b0 + 4*SW;

    float4 xc0[NC4], xc1[NC4];
    #pragma unroll
    for (int c4 = 0; c4 < NC4; ++c4) {
        xc0[c4] = xs4[c4*CPLANE + b0];
        xc1[c4] = xs4[c4*CPLANE + b1];
    }

    u64 accA[8], accB[8];
    #pragma unroll
    for (int q = 0; q < 8; ++q) {
        u64 seed = pack2(cbs[ph*16 + 2*q], cbs[ph*16 + 2*q + 1]);
        accA[q] = seed;
        accB[q] = seed;
    }

    #pragma unroll 1
    for (int r = 0; r < NSEL; ++r) {
        const int a0 = b0 + (int)selp[r*NTHR + pp]       - 512;
        const int a1 = b1 + (int)selp[r*NTHR + pp + 128] - 512;
        const ulonglong2* wq =
            reinterpret_cast<const ulonglong2*>(ws + (r << 9) + (ph << 4));
        #pragma unroll
        for (int c4 = 0; c4 < NC4; ++c4) {
            const float4 v0 = xs4[c4*CPLANE + a0];
            const float4 v1 = xs4[c4*CPLANE + a1];
            u64 dA, dB;
            #define CH_BLOCK(comp, choff)                                        \
            {                                                                    \
                dA = pack2(xc0[c4].comp - v0.comp, xc0[c4].comp - v0.comp);      \
                dB = pack2(xc1[c4].comp - v1.comp, xc1[c4].comp - v1.comp);      \
                const ulonglong2* wc_ = wq + (4*c4 + (choff))*8;                 \
                ulonglong2 w0 = wc_[0], w1 = wc_[1], w2 = wc_[2], w3 = wc_[3];   \
                fma2(accA[0], w0.x, dA); fma2(accB[0], w0.x, dB);                \
                fma2(accA[1], w0.y, dA); fma2(accB[1], w0.y, dB);                \
                fma2(accA[2], w1.x, dA); fma2(accB[2], w1.x, dB);                \
                fma2(accA[3], w1.y, dA); fma2(accB[3], w1.y, dB);                \
                fma2(accA[4], w2.x, dA); fma2(accB[4], w2.x, dB);                \
                fma2(accA[5], w2.y, dA); fma2(accB[5], w2.y, dB);                \
                fma2(accA[6], w3.x, dA); fma2(accB[6], w3.x, dB);                \
                fma2(accA[7], w3.y, dA); fma2(accB[7], w3.y, dB);                \
            }
            CH_BLOCK(x, 0)
            CH_BLOCK(y, 1)
            CH_BLOCK(z, 2)
            CH_BLOCK(w, 3)
            #undef CH_BLOCK
        }
    }

    // ---- store: 16 o-channels x 2 pixels ----
    const int gx = gx0 + px;
    const int gy_a = gy0 + py;
    const int gy_b = gy_a + 4;
    float* ob = out + (size_t)bz*OUTC*HW + (size_t)(ph*16)*HW + gx;
    #pragma unroll
    for (int q = 0; q < 8; ++q) {
        float2 va = unpack2(accA[q]);
        float2 vb = unpack2(accB[q]);
        ob[(2*q  )*HW + gy_a*WWIDTH] = va.x;
        ob[(2*q+1)*HW + gy_a*WWIDTH] = va.y;
        ob[(2*q  )*HW + gy_b*WWIDTH] = vb.x;
        ob[(2*q+1)*HW + gy_b*WWIDTH] = vb.y;
    }
}

extern "C" void kernel_launch(void* const* d_in, const int* in_sizes, int n_in,
                              void* d_out, int out_size)
{
    const float* x  = (const float*)d_in[0];
    const float* cw = (const float*)d_in[1];
    const float* cb = (const float*)d_in[2];
    float* out = (float*)d_out;

    cudaFuncSetAttribute(pkc2d_kernel,
                         cudaFuncAttributeMaxDynamicSharedMemorySize, SMEM_BYTES);

    dim3 block(TW, TH, 1);
    dim3 grid(WWIDTH/TW, HH/TH, B_);
    pkc2d_kernel<<<grid, block, SMEM_BYTES>>>(x, cw, cb, out);
}

// round 13
// speedup vs baseline: 1.1584x; 1.0167x over previous
#include <cuda_runtime.h>
#include <math.h>

// x (2,16,256,256) f32, conv_w (32,16,4,4), conv_b (32) -> out (2,32,256,256) f32.
// Ring of 40 offsets (radius 5), stable-select 16 smallest sigmoid-sims,
// rank-indexed 32x(16*16) mat-vec per pixel.
// R12 structure (float4 channel-grouped halo, LDS.128 gathers) with
// __expf sigmoid (MUFU.EX2; |s|<~1 so error ~2-3 ulp, comparable to libm).

#define B_      2
#define CCH     16
#define NC4     (CCH/4)        // 4 float4 channel-groups
#define HH      256
#define WWIDTH  256
#define HW      (HH*WWIDTH)
#define OUTC    32
#define NOFF    40
#define NSEL    16

#define TW 32
#define TH 8
#define NTHR (TW*TH)           // 256
#define SW 42                  // TW + 2*5
#define SH 18                  // TH + 2*5
#define CPLANE (SW*SH)         // 756
#define XS_FLOATS (CPLANE*CCH)        // 12096
#define WS_FLOATS (NSEL*CCH*OUTC)     // 8192
#define CB_FLOATS 32
// smem: xs + ws + cbs + selp(u16 [rank][tid] = 8192B)
#define SMEM_BYTES ((XS_FLOATS + WS_FLOATS + CB_FLOATS)*4 + NSEL*NTHR*2)

// Ring offsets, order matching _prf_offsets:
//  j 0..10 : dx=-5,   dy=j-5
//  j 11..19: dx=j-15, dy=+5
//  j 20..30: dx=+5,   dy=j-25
//  j 31..39: dx=j-35, dy=-5
__host__ __device__ constexpr int dxOf(int j){ return j<11 ? -5 : (j<20 ? j-15 : (j<31 ? 5 : j-35)); }
__host__ __device__ constexpr int dyOf(int j){ return j<11 ? j-5 : (j<20 ? 5 : (j<31 ? j-25 : -5)); }
__host__ __device__ constexpr int offOf(int j){ return dxOf(j)*SW + dyOf(j); }

typedef unsigned long long u64;

__device__ __forceinline__ u64 pack2(float a, float b){
    u64 r;
    asm("mov.b64 %0, {%1,%2};" : "=l"(r) : "f"(a), "f"(b));
    return r;
}
__device__ __forceinline__ void fma2(u64 &acc, u64 a, u64 b){
    asm("fma.rn.f32x2 %0, %1, %2, %0;" : "+l"(acc) : "l"(a), "l"(b));
}
__device__ __forceinline__ float2 unpack2(u64 v){
    float2 f;
    asm("mov.b64 {%0,%1}, %2;" : "=f"(f.x), "=f"(f.y) : "l"(v));
    return f;
}

__global__ __launch_bounds__(NTHR, 2)
void pkc2d_kernel(const float* __restrict__ x,
                  const float* __restrict__ cw,
                  const float* __restrict__ cb,
                  float* __restrict__ out)
{
    extern __shared__ float sm[];
    float4*         xs4  = reinterpret_cast<float4*>(sm);       // [c4][plane]
    float*          ws   = sm + XS_FLOATS;                      // [r][c][o]
    float*          cbs  = ws + WS_FLOATS;                      // [32]
    unsigned short* selp = (unsigned short*)(cbs + CB_FLOATS);  // [rank][tid]

    const int tx = threadIdx.x, ty = threadIdx.y;
    const int tid = ty*TW + tx;
    const int gx0 = blockIdx.x*TW, gy0 = blockIdx.y*TH;
    const int bz  = blockIdx.z;

    const float* xb = x + (size_t)bz * CCH * HW;

    // ---- cooperative halo load: 4-channel float4 groups ----
    for (int i = tid; i < CPLANE*NC4; i += NTHR) {
        int c4   = i / CPLANE;
        int cell = i - c4*CPLANE;
        int sy   = cell / SW;
        int sx   = cell - sy*SW;
        int gy   = gy0 + sy - 5;
        int gxp  = gx0 + sx - 5;
        float4 v = make_float4(0.f, 0.f, 0.f, 0.f);
        if ((unsigned)gy < (unsigned)HH && (unsigned)gxp < (unsigned)WWIDTH) {
            const float* p = xb + (4*c4)*HW + gy*WWIDTH + gxp;
            v.x = p[0];
            v.y = p[HW];
            v.z = p[2*HW];
            v.w = p[3*HW];
        }
        xs4[i] = v;
    }
    // ws[((r*16)+c)*32 + o] = cw[o*256 + c*16 + r]
    for (int i = tid; i < WS_FLOATS; i += NTHR) {
        int o  = i & 31;
        int rc = i >> 5;
        int r  = rc >> 4;
        int c  = rc & 15;
        ws[i] = cw[o*256 + c*16 + r];
    }
    if (tid < 32) cbs[tid] = cb[tid];
    __syncthreads();

    // ================= Phase 1: selection =================
    {
        const int base = (ty+5)*SW + (tx+5);

        float4 xc[NC4];
        #pragma unroll
        for (int c4 = 0; c4 < NC4; ++c4) xc[c4] = xs4[c4*CPLANE + base];

        // sims: sequential channel-order mul+add (matches reference reduction),
        // then sigmoid — REQUIRED: its fp32 rounding creates index-broken ties
        // (verified R5). __expf: |s| < ~1 so MUFU.EX2 error ~2-3 ulp, same
        // magnitude as libm-vs-reference divergence. __frcp_rn bit-identical
        // to 1.0f/x (verified R9).
        float sims[NOFF];
        #pragma unroll
        for (int j = 0; j < NOFF; ++j) {
            const int off = offOf(j);
            float s = 0.f;
            #pragma unroll
            for (int c4 = 0; c4 < NC4; ++c4) {
                const float4 v = xs4[c4*CPLANE + base + off];
                s = __fadd_rn(s, __fmul_rn(v.x, xc[c4].x));
                s = __fadd_rn(s, __fmul_rn(v.y, xc[c4].y));
                s = __fadd_rn(s, __fmul_rn(v.z, xc[c4].z));
                s = __fadd_rn(s, __fmul_rn(v.w, xc[c4].w));
            }
            s *= 0.0625f;
            sims[j] = __frcp_rn(1.0f + __expf(-s));
        }

        // Stable argsort rank, one compare per unordered pair (proven R4/R6).
        int rk[NOFF];
        #pragma unroll
        for (int i = 0; i < NOFF; ++i) rk[i] = NOFF - 1 - i;
        #pragma unroll
        for (int i = 0; i < NOFF; ++i) {
            #pragma unroll
            for (int j = i+1; j < NOFF; ++j) {
                if (sims[i] <= sims[j]) { rk[j] += 1; rk[i] -= 1; }
            }
        }
        #pragma unroll
        for (int j = 0; j < NOFF; ++j) {
            if (rk[j] < NSEL)
                selp[rk[j]*NTHR + tid] = (unsigned short)(offOf(j) + 512);
        }
    }
    __syncthreads();

    // ================= Phase 2: pixel-pair / half-OUTC mat-vec =================
    // thread t: ph = t>>7 -> o in [16*ph, 16*ph+16); pixels p0 = t&127 (rows 0..3)
    // and p1 = p0+128 (rows 4..7) of the 32x8 tile.
    const int pp = tid & 127;
    const int ph = tid >> 7;
    const int px = pp & 31;
    const int py = pp >> 5;

    const int b0 = (py+5)*SW + (px+5);
    const int b1 = b0 + 4*SW;

    float4 xc0[NC4], xc1[NC4];
    #pragma unroll
    for (int c4 = 0; c4 < NC4; ++c4) {
        xc0[c4] = xs4[c4*CPLANE + b0];
        xc1[c4] = xs4[c4*CPLANE + b1];
    }

    u64 accA[8], accB[8];
    #pragma unroll
    for (int q = 0; q < 8; ++q) {
        u64 seed = pack2(cbs[ph*16 + 2*q], cbs[ph*16 + 2*q + 1]);
        accA[q] = seed;
        accB[q] = seed;
    }

    #pragma unroll 1
    for (int r = 0; r < NSEL; ++r) {
        const int a0 = b0 + (int)selp[r*NTHR + pp]       - 512;
        const int a1 = b1 + (int)selp[r*NTHR + pp + 128] - 512;
        const ulonglong2* wq =
            reinterpret_cast<const ulonglong2*>(ws + (r << 9) + (ph << 4));
        #pragma unroll
        for (int c4 = 0; c4 < NC4; ++c4) {
            const float4 v0 = xs4[c4*CPLANE + a0];
            const float4 v1 = xs4[c4*CPLANE + a1];
            u64 dA, dB;
            #define CH_BLOCK(comp, choff)                                        \
            {                                                                    \
                dA = pack2(xc0[c4].comp - v0.comp, xc0[c4].comp - v0.comp);      \
                dB = pack2(xc1[c4].comp - v1.comp, xc1[c4].comp - v1.comp);      \
                const ulonglong2* wc_ = wq + (4*c4 + (choff))*8;                 \
                ulonglong2 w0 = wc_[0], w1 = wc_[1], w2 = wc_[2], w3 = wc_[3];   \
                fma2(accA[0], w0.x, dA); fma2(accB[0], w0.x, dB);                \
                fma2(accA[1], w0.y, dA); fma2(accB[1], w0.y, dB);                \
                fma2(accA[2], w1.x, dA); fma2(accB[2], w1.x, dB);                \
                fma2(accA[3], w1.y, dA); fma2(accB[3], w1.y, dB);                \
                fma2(accA[4], w2.x, dA); fma2(accB[4], w2.x, dB);                \
                fma2(accA[5], w2.y, dA); fma2(accB[5], w2.y, dB);                \
                fma2(accA[6], w3.x, dA); fma2(accB[6], w3.x, dB);                \
                fma2(accA[7], w3.y, dA); fma2(accB[7], w3.y, dB);                \
            }
            CH_BLOCK(x, 0)
            CH_BLOCK(y, 1)
            CH_BLOCK(z, 2)
            CH_BLOCK(w, 3)
            #undef CH_BLOCK
        }
    }

    // ---- store: 16 o-channels x 2 pixels ----
    const int gx = gx0 + px;
    const int gy_a = gy0 + py;
    const int gy_b = gy_a + 4;
    float* ob = out + (size_t)bz*OUTC*HW + (size_t)(ph*16)*HW + gx;
    #pragma unroll
    for (int q = 0; q < 8; ++q) {
        float2 va = unpack2(accA[q]);
        float2 vb = unpack2(accB[q]);
        ob[(2*q  )*HW + gy_a*WWIDTH] = va.x;
        ob[(2*q+1)*HW + gy_a*WWIDTH] = va.y;
        ob[(2*q  )*HW + gy_b*WWIDTH] = vb.x;
        ob[(2*q+1)*HW + gy_b*WWIDTH] = vb.y;
    }
}

extern "C" void kernel_launch(void* const* d_in, const int* in_sizes, int n_in,
                              void* d_out, int out_size)
{
    const float* x  = (const float*)d_in[0];
    const float* cw = (const float*)d_in[1];
    const float* cb = (const float*)d_in[2];
    float* out = (float*)d_out;

    cudaFuncSetAttribute(pkc2d_kernel,
                         cudaFuncAttributeMaxDynamicSharedMemorySize, SMEM_BYTES);

    dim3 block(TW, TH, 1);
    dim3 grid(WWIDTH/TW, HH/TH, B_);
    pkc2d_kernel<<<grid, block, SMEM_BYTES>>>(x, cw, cb, out);
}

// round 14
// speedup vs baseline: 1.1661x; 1.0067x over previous
#include <cuda_runtime.h>
#include <math.h>

// x (2,16,256,256) f32, conv_w (32,16,4,4), conv_b (32) -> out (2,32,256,256) f32.
// Ring of 40 offsets (radius 5), stable-select 16 smallest sigmoid-sims,
// rank-indexed 32x(16*16) mat-vec per pixel.
// R13 structure (float4 halo, LDS.128 gathers, __expf sigmoid) with:
//  - FFMA-contracted sim dot (sequential channel order, fused rounding)
//  - 1/16 scale folded into exp argument (bit-identical: exact pow2 scaling)

#define B_      2
#define CCH     16
#define NC4     (CCH/4)        // 4 float4 channel-groups
#define HH      256
#define WWIDTH  256
#define HW      (HH*WWIDTH)
#define OUTC    32
#define NOFF    40
#define NSEL    16

#define TW 32
#define TH 8
#define NTHR (TW*TH)           // 256
#define SW 42                  // TW + 2*5
#define SH 18                  // TH + 2*5
#define CPLANE (SW*SH)         // 756
#define XS_FLOATS (CPLANE*CCH)        // 12096
#define WS_FLOATS (NSEL*CCH*OUTC)     // 8192
#define CB_FLOATS 32
// smem: xs + ws + cbs + selp(u16 [rank][tid] = 8192B)
#define SMEM_BYTES ((XS_FLOATS + WS_FLOATS + CB_FLOATS)*4 + NSEL*NTHR*2)

// Ring offsets, order matching _prf_offsets:
//  j 0..10 : dx=-5,   dy=j-5
//  j 11..19: dx=j-15, dy=+5
//  j 20..30: dx=+5,   dy=j-25
//  j 31..39: dx=j-35, dy=-5
__host__ __device__ constexpr int dxOf(int j){ return j<11 ? -5 : (j<20 ? j-15 : (j<31 ? 5 : j-35)); }
__host__ __device__ constexpr int dyOf(int j){ return j<11 ? j-5 : (j<20 ? 5 : (j<31 ? j-25 : -5)); }
__host__ __device__ constexpr int offOf(int j){ return dxOf(j)*SW + dyOf(j); }

typedef unsigned long long u64;

__device__ __forceinline__ u64 pack2(float a, float b){
    u64 r;
    asm("mov.b64 %0, {%1,%2};" : "=l"(r) : "f"(a), "f"(b));
    return r;
}
__device__ __forceinline__ void fma2(u64 &acc, u64 a, u64 b){
    asm("fma.rn.f32x2 %0, %1, %2, %0;" : "+l"(acc) : "l"(a), "l"(b));
}
__device__ __forceinline__ float2 unpack2(u64 v){
    float2 f;
    asm("mov.b64 {%0,%1}, %2;" : "=f"(f.x), "=f"(f.y) : "l"(v));
    return f;
}

__global__ __launch_bounds__(NTHR, 2)
void pkc2d_kernel(const float* __restrict__ x,
                  const float* __restrict__ cw,
                  const float* __restrict__ cb,
                  float* __restrict__ out)
{
    extern __shared__ float sm[];
    float4*         xs4  = reinterpret_cast<float4*>(sm);       // [c4][plane]
    float*          ws   = sm + XS_FLOATS;                      // [r][c][o]
    float*          cbs  = ws + WS_FLOATS;                      // [32]
    unsigned short* selp = (unsigned short*)(cbs + CB_FLOATS);  // [rank][tid]

    const int tx = threadIdx.x, ty = threadIdx.y;
    const int tid = ty*TW + tx;
    const int gx0 = blockIdx.x*TW, gy0 = blockIdx.y*TH;
    const int bz  = blockIdx.z;

    const float* xb = x + (size_t)bz * CCH * HW;

    // ---- cooperative halo load: 4-channel float4 groups ----
    for (int i = tid; i < CPLANE*NC4; i += NTHR) {
        int c4   = i / CPLANE;
        int cell = i - c4*CPLANE;
        int sy   = cell / SW;
        int sx   = cell - sy*SW;
        int gy   = gy0 + sy - 5;
        int gxp  = gx0 + sx - 5;
        float4 v = make_float4(0.f, 0.f, 0.f, 0.f);
        if ((unsigned)gy < (unsigned)HH && (unsigned)gxp < (unsigned)WWIDTH) {
            const float* p = xb + (4*c4)*HW + gy*WWIDTH + gxp;
            v.x = p[0];
            v.y = p[HW];
            v.z = p[2*HW];
            v.w = p[3*HW];
        }
        xs4[i] = v;
    }
    // ws[((r*16)+c)*32 + o] = cw[o*256 + c*16 + r]
    for (int i = tid; i < WS_FLOATS; i += NTHR) {
        int o  = i & 31;
        int rc = i >> 5;
        int r  = rc >> 4;
        int c  = rc & 15;
        ws[i] = cw[o*256 + c*16 + r];
    }
    if (tid < 32) cbs[tid] = cb[tid];
    __syncthreads();

    // ================= Phase 1: selection =================
    {
        const int base = (ty+5)*SW + (tx+5);

        float4 xc[NC4];
        #pragma unroll
        for (int c4 = 0; c4 < NC4; ++c4) xc[c4] = xs4[c4*CPLANE + base];

        // sims: FFMA-contracted sequential channel-order dot, then sigmoid.
        // Sigmoid REQUIRED (verified R5: its rounding creates index-broken
        // ties). R13 verified ~2-ulp exp perturbation flips zero selections;
        // FFMA perturbs s by <=1 ulp — same robustness class.
        // exp fold: s*0.0625 exact (pow2) and 0.0625*log2e rounds exactly,
        // so __expf(s*-0.0625f) is bit-identical to __expf(-(s*0.0625f)).
        float sims[NOFF];
        #pragma unroll
        for (int j = 0; j < NOFF; ++j) {
            const int off = offOf(j);
            float s = 0.f;
            #pragma unroll
            for (int c4 = 0; c4 < NC4; ++c4) {
                const float4 v = xs4[c4*CPLANE + base + off];
                s = __fmaf_rn(v.x, xc[c4].x, s);
                s = __fmaf_rn(v.y, xc[c4].y, s);
                s = __fmaf_rn(v.z, xc[c4].z, s);
                s = __fmaf_rn(v.w, xc[c4].w, s);
            }
            sims[j] = __frcp_rn(1.0f + __expf(s * -0.0625f));
        }

        // Stable argsort rank, one compare per unordered pair (proven R4/R6).
        int rk[NOFF];
        #pragma unroll
        for (int i = 0; i < NOFF; ++i) rk[i] = NOFF - 1 - i;
        #pragma unroll
        for (int i = 0; i < NOFF; ++i) {
            #pragma unroll
            for (int j = i+1; j < NOFF; ++j) {
                if (sims[i] <= sims[j]) { rk[j] += 1; rk[i] -= 1; }
            }
        }
        #pragma unroll
        for (int j = 0; j < NOFF; ++j) {
            if (rk[j] < NSEL)
                selp[rk[j]*NTHR + tid] = (unsigned short)(offOf(j) + 512);
        }
    }
    __syncthreads();

    // ================= Phase 2: pixel-pair / half-OUTC mat-vec =================
    // thread t: ph = t>>7 -> o in [16*ph, 16*ph+16); pixels p0 = t&127 (rows 0..3)
    // and p1 = p0+128 (rows 4..7) of the 32x8 tile.
    const int pp = tid & 127;
    const int ph = tid >> 7;
    const int px = pp & 31;
    const int py = pp >> 5;

    const int b0 = (py+5)*SW + (px+5);
    const int b1 = b0 + 4*SW;

    float4 xc0[NC4], xc1[NC4];
    #pragma unroll
    for (int c4 = 0; c4 < NC4; ++c4) {
        xc0[c4] = xs4[c4*CPLANE + b0];
        xc1[c4] = xs4[c4*CPLANE + b1];
    }

    u64 accA[8], accB[8];
    #pragma unroll
    for (int q = 0; q < 8; ++q) {
        u64 seed = pack2(cbs[ph*16 + 2*q], cbs[ph*16 + 2*q + 1]);
        accA[q] = seed;
        accB[q] = seed;
    }

    #pragma unroll 1
    for (int r = 0; r < NSEL; ++r) {
        const int a0 = b0 + (int)selp[r*NTHR + pp]       - 512;
        const int a1 = b1 + (int)selp[r*NTHR + pp + 128] - 512;
        const ulonglong2* wq =
            reinterpret_cast<const ulonglong2*>(ws + (r << 9) + (ph << 4));
        #pragma unroll
        for (int c4 = 0; c4 < NC4; ++c4) {
            const float4 v0 = xs4[c4*CPLANE + a0];
            const float4 v1 = xs4[c4*CPLANE + a1];
            u64 dA, dB;
            #define CH_BLOCK(comp, choff)                                        \
            {                                                                    \
                dA = pack2(xc0[c4].comp - v0.comp, xc0[c4].comp - v0.comp);      \
                dB = pack2(xc1[c4].comp - v1.comp, xc1[c4].comp - v1.comp);      \
                const ulonglong2* wc_ = wq + (4*c4 + (choff))*8;                 \
                ulonglong2 w0 = wc_[0], w1 = wc_[1], w2 = wc_[2], w3 = wc_[3];   \
                fma2(accA[0], w0.x, dA); fma2(accB[0], w0.x, dB);                \
                fma2(accA[1], w0.y, dA); fma2(accB[1], w0.y, dB);                \
                fma2(accA[2], w1.x, dA); fma2(accB[2], w1.x, dB);                \
                fma2(accA[3], w1.y, dA); fma2(accB[3], w1.y, dB);                \
                fma2(accA[4], w2.x, dA); fma2(accB[4], w2.x, dB);                \
                fma2(accA[5], w2.y, dA); fma2(accB[5], w2.y, dB);                \
                fma2(accA[6], w3.x, dA); fma2(accB[6], w3.x, dB);                \
                fma2(accA[7], w3.y, dA); fma2(accB[7], w3.y, dB);                \
            }
            CH_BLOCK(x, 0)
            CH_BLOCK(y, 1)
            CH_BLOCK(z, 2)
            CH_BLOCK(w, 3)
            #undef CH_BLOCK
        }
    }

    // ---- store: 16 o-channels x 2 pixels ----
    const int gx = gx0 + px;
    const int gy_a = gy0 + py;
    const int gy_b = gy_a + 4;
    float* ob = out + (size_t)bz*OUTC*HW + (size_t)(ph*16)*HW + gx;
    #pragma unroll
    for (int q = 0; q < 8; ++q) {
        float2 va = unpack2(accA[q]);
        float2 vb = unpack2(accB[q]);
        ob[(2*q  )*HW + gy_a*WWIDTH] = va.x;
        ob[(2*q+1)*HW + gy_a*WWIDTH] = va.y;
        ob[(2*q  )*HW + gy_b*WWIDTH] = vb.x;
        ob[(2*q+1)*HW + gy_b*WWIDTH] = vb.y;
    }
}

extern "C" void kernel_launch(void* const* d_in, const int* in_sizes, int n_in,
                              void* d_out, int out_size)
{
    const float* x  = (const float*)d_in[0];
    const float* cw = (const float*)d_in[1];
    const float* cb = (const float*)d_in[2];
    float* out = (float*)d_out;

    cudaFuncSetAttribute(pkc2d_kernel,
                         cudaFuncAttributeMaxDynamicSharedMemorySize, SMEM_BYTES);

    dim3 block(TW, TH, 1);
    dim3 grid(WWIDTH/TW, HH/TH, B_);
    pkc2d_kernel<<<grid, block, SMEM_BYTES>>>(x, cw, cb, out);
}